// round 5
// baseline (speedup 1.0000x reference)
#include <cuda_runtime.h>

// Spherical harmonics (no sphericart), L_MAX = 8, output [N, 81] fp32.
// HBM-write-bound: stage per-block output tile in smem, then coalesced float4 stores.

#define LMAX 8
#define NSH  81      // (LMAX+1)^2
#define NQ   45      // (LMAX+1)(LMAX+2)/2
#define BLK  128

__global__ __launch_bounds__(BLK)
void sh_kernel(const float* __restrict__ xyz,
               const float* __restrict__ F,
               float* __restrict__ out,
               int n)
{
    __shared__ float sbuf[BLK * NSH];   // 41472 B; row stride 81 floats (odd mod 32) -> conflict-free
    __shared__ float sF[NQ];

    const int tid     = threadIdx.x;
    const int base_pt = blockIdx.x * BLK;
    const int i       = base_pt + tid;

    if (tid < NQ) sF[tid] = F[tid];
    __syncthreads();

    if (i < n) {
        const float X = xyz[3 * i + 0];
        const float Y = xyz[3 * i + 1];
        const float Z = xyz[3 * i + 2];
        const float rinv = rsqrtf(X * X + Y * Y + Z * Z);
        const float x = X * rinv, y = Y * rinv, z = Z * rinv;

        // Associated-Legendre-style Q recurrence (matches reference op-for-op in fp32)
        float Q[NQ];
        Q[0] = 1.0f;
        #pragma unroll
        for (int l = 1; l <= LMAX; ++l) {
            const int tl  = l * (l + 1) / 2;
            const int tl1 = (l - 1) * l / 2;
            const int tl2 = (l - 2) * (l - 1) / 2;
            Q[tl + l]     = -(2.0f * l - 1.0f) * Q[tl1 + l - 1];   // constant-folded
            Q[tl + l - 1] = -z * Q[tl + l];
            #pragma unroll
            for (int m = 0; m <= l - 2; ++m) {
                Q[tl + m] = ((2.0f * l - 1.0f) * z * Q[tl1 + m]
                             - (float)(l + m - 1) * Q[tl2 + m]) * (1.0f / (float)(l - m));
            }
        }

        // sin/cos multiple-angle recurrence
        float s[LMAX + 1], c[LMAX + 1];
        s[0] = 0.0f; c[0] = 1.0f;
        #pragma unroll
        for (int m = 1; m <= LMAX; ++m) {
            s[m] = x * s[m - 1] + y * c[m - 1];
            c[m] = x * c[m - 1] - y * s[m - 1];
        }

        const float inv_sqrt2 = 0.70710678118654752440f;
        float* o = &sbuf[tid * NSH];
        #pragma unroll
        for (int l = 0; l <= LMAX; ++l) {
            const int base = l * (l + 1) / 2;
            const int col0 = l * l;
            #pragma unroll
            for (int m = -l; m < 0; ++m)
                o[col0 + l + m] = sF[base - m] * Q[base - m] * s[-m];
            o[col0 + l] = sF[base] * Q[base] * inv_sqrt2;
            #pragma unroll
            for (int m = 1; m <= l; ++m)
                o[col0 + l + m] = sF[base + m] * Q[base + m] * c[m];
        }
    }
    __syncthreads();

    // Coalesced block-tile writeback: vector body + scalar tail (tail only on ragged last block)
    const int npts  = min(BLK, n - base_pt);
    const int total = npts * NSH;
    float* gout = out + (size_t)base_pt * NSH;   // base_pt*81*4 B; base_pt%4==0 -> 16B aligned
    const int n4 = total >> 2;
    {
        float4* g4 = (float4*)gout;
        const float4* s4 = (const float4*)sbuf;
        for (int k = tid; k < n4; k += BLK)
            g4[k] = s4[k];
    }
    for (int k = (n4 << 2) + tid; k < total; k += BLK)
        gout[k] = sbuf[k];
}

extern "C" void kernel_launch(void* const* d_in, const int* in_sizes, int n_in,
                              void* d_out, int out_size)
{
    const float* xyz = (const float*)d_in[0];
    const float* F   = (const float*)d_in[1];
    float* out       = (float*)d_out;
    const int n      = in_sizes[0] / 3;
    if (n <= 0) return;
    const int grid   = (n + BLK - 1) / BLK;
    sh_kernel<<<grid, BLK>>>(xyz, F, out, n);
}

// round 6
// speedup vs baseline: 1.4677x; 1.4677x over previous
#include <cuda_runtime.h>

// Spherical harmonics (L_MAX=8), output [N, 81] fp32.
// Persistent-CTA software pipeline: stores of tile t drain to DRAM while
// tile t+1 computes, smoothing the DRAM write duty cycle (was 39% active).

#define LMAX 8
#define NSH  81      // (LMAX+1)^2
#define NQ   45      // (LMAX+1)(LMAX+2)/2
#define BLK  128
#define MAX_CTAS (148 * 5)   // 5 CTAs/SM (smem-limited), 148 SMs

__global__ __launch_bounds__(BLK)
void sh_kernel(const float* __restrict__ xyz,
               const float* __restrict__ F,
               float* __restrict__ out,
               int n, int ntiles)
{
    __shared__ float sbuf[BLK * NSH];   // 41472 B; row stride 81 (odd) -> conflict-free STS
    __shared__ float sF[NQ];

    const int tid = threadIdx.x;
    if (tid < NQ) sF[tid] = F[tid];
    __syncthreads();

    // Prefetch first tile's xyz
    int t = blockIdx.x;
    float X = 0.f, Y = 0.f, Z = 0.f;
    bool act = false;
    {
        const int i = t * BLK + tid;
        if (t < ntiles && i < n) {
            act = true;
            X = xyz[3 * i + 0];
            Y = xyz[3 * i + 1];
            Z = xyz[3 * i + 2];
        }
    }

    while (t < ntiles) {
        // ---- compute phase (overlaps with previous tile's in-flight stores) ----
        if (act) {
            const float rinv = rsqrtf(X * X + Y * Y + Z * Z);
            const float x = X * rinv, y = Y * rinv, z = Z * rinv;

            float Q[NQ];
            Q[0] = 1.0f;
            #pragma unroll
            for (int l = 1; l <= LMAX; ++l) {
                const int tl  = l * (l + 1) / 2;
                const int tl1 = (l - 1) * l / 2;
                const int tl2 = (l - 2) * (l - 1) / 2;
                Q[tl + l]     = -(2.0f * l - 1.0f) * Q[tl1 + l - 1];
                Q[tl + l - 1] = -z * Q[tl + l];
                #pragma unroll
                for (int m = 0; m <= l - 2; ++m) {
                    Q[tl + m] = ((2.0f * l - 1.0f) * z * Q[tl1 + m]
                                 - (float)(l + m - 1) * Q[tl2 + m]) * (1.0f / (float)(l - m));
                }
            }

            float s[LMAX + 1], c[LMAX + 1];
            s[0] = 0.0f; c[0] = 1.0f;
            #pragma unroll
            for (int m = 1; m <= LMAX; ++m) {
                s[m] = x * s[m - 1] + y * c[m - 1];
                c[m] = x * c[m - 1] - y * s[m - 1];
            }

            const float inv_sqrt2 = 0.70710678118654752440f;
            float* o = &sbuf[tid * NSH];
            #pragma unroll
            for (int l = 0; l <= LMAX; ++l) {
                const int base = l * (l + 1) / 2;
                const int col0 = l * l;
                #pragma unroll
                for (int m = -l; m < 0; ++m)
                    o[col0 + l + m] = sF[base - m] * Q[base - m] * s[-m];
                o[col0 + l] = sF[base] * Q[base] * inv_sqrt2;
                #pragma unroll
                for (int m = 1; m <= l; ++m)
                    o[col0 + l + m] = sF[base + m] * Q[base + m] * c[m];
            }
        }
        __syncthreads();

        // ---- prefetch next tile's xyz (read latency hides under the drain) ----
        const int tn = t + gridDim.x;
        bool actn = false;
        float Xn = 0.f, Yn = 0.f, Zn = 0.f;
        if (tn < ntiles) {
            const int i2 = tn * BLK + tid;
            if (i2 < n) {
                actn = true;
                Xn = xyz[3 * i2 + 0];
                Yn = xyz[3 * i2 + 1];
                Zn = xyz[3 * i2 + 2];
            }
        }

        // ---- drain phase: coalesced float4 writeback of the contiguous tile ----
        {
            const int base_pt = t * BLK;
            const int npts  = min(BLK, n - base_pt);
            const int total = npts * NSH;
            float* gout = out + (size_t)base_pt * NSH;  // 16B-aligned (base_pt*81*4)
            const int n4 = total >> 2;
            float4* g4 = (float4*)gout;
            const float4* s4 = (const float4*)sbuf;
            for (int k = tid; k < n4; k += BLK)
                g4[k] = s4[k];
            for (int k = (n4 << 2) + tid; k < total; k += BLK)
                gout[k] = sbuf[k];
        }
        __syncthreads();   // LDS side of drain complete for all warps -> sbuf reusable

        t = tn; act = actn; X = Xn; Y = Yn; Z = Zn;
    }
}

extern "C" void kernel_launch(void* const* d_in, const int* in_sizes, int n_in,
                              void* d_out, int out_size)
{
    const float* xyz = (const float*)d_in[0];
    const float* F   = (const float*)d_in[1];
    float* out       = (float*)d_out;
    const int n      = in_sizes[0] / 3;
    if (n <= 0) return;
    const int ntiles = (n + BLK - 1) / BLK;
    const int grid   = ntiles < MAX_CTAS ? ntiles : MAX_CTAS;
    sh_kernel<<<grid, BLK>>>(xyz, F, out, n, ntiles);
}